// round 1
// baseline (speedup 1.0000x reference)
#include <cuda_runtime.h>
#include <math.h>

// Problem dims
#define BB 128
#define HH 1024
#define SS 256
#define VV 32000
#define H3 3072
#define H2 2048

// Output layout: (output[B,V], new_hidden[2,B,H], attn[B,1,S]) flattened
#define OUT_HID  (BB*VV)
#define OUT_ATTN (BB*VV + 2*BB*HH)

// ---- scratch (__device__ globals: sanctioned scratch, no runtime alloc) ----
__device__ float g_x[BB*HH];        // embedded input
__device__ float g_gi[BB*H3];       // input-gate preacts
__device__ float g_gh[BB*H3];       // hidden-gate preacts
__device__ float g_h0[BB*HH];       // layer-0 output
__device__ float g_concat[BB*H2];   // [h1 | context]
__device__ float g_u2[HH];          // W_attn[:,H:2H]^T v
__device__ float g_cout[BB*HH];     // tanh(concat @ W_concat^T + b)
__device__ float g_part[4*BB*H3];   // K-split partials (max 4*128*3072)

// ---------------- embedding gather ----------------
__global__ void k_embed(const int* __restrict__ ids, const float* __restrict__ tab) {
    int b = blockIdx.x;
    long row = ids[b];
    const float4* src = (const float4*)(tab + row * (long)HH);
    float4* dst = (float4*)(g_x + b * HH);
    for (int i = threadIdx.x; i < HH/4; i += blockDim.x) dst[i] = src[i];
}

// ---------------- u2[e] = sum_h v[h] * W_attn[h, H+e] ----------------
__global__ void k_u2(const float* __restrict__ W_attn, const float* __restrict__ v) {
    int e = blockIdx.x * blockDim.x + threadIdx.x;  // 0..1023
    float acc = 0.f;
    #pragma unroll 4
    for (int h = 0; h < HH; h++) acc += v[h] * W_attn[h * H2 + HH + e];
    g_u2[e] = acc;
}

// ---------------- generic NT SGEMM: C[M,N] = A[M,K] * B[N,K]^T ----------------
// 64x64 tile, BK=16, 256 threads, 4x4 microtile. gridDim.z = K-split.
// If gridDim.z==1: writes C with bias (+optional tanh). Else writes g_part[z].
__global__ void __launch_bounds__(256) k_gemm_nt(
    const float* __restrict__ A, const float* __restrict__ Bm,
    float* __restrict__ C, const float* __restrict__ bias,
    int M, int N, int K, int epi)
{
    __shared__ __align__(16) float As[16][68];
    __shared__ __align__(16) float Bs[16][68];

    int tid = threadIdx.x;
    int tx = tid & 15, ty = tid >> 4;
    int n0 = blockIdx.x * 64, m0 = blockIdx.y * 64;
    int ksplit = gridDim.z;
    int klen = K / ksplit;
    int kb = blockIdx.z * klen;

    int lr = tid >> 2;         // 0..63
    int lc = (tid & 3) * 4;    // 0,4,8,12

    const float* Ag = A + (size_t)(m0 + lr) * K + kb + lc;
    const float* Bg = Bm + (size_t)(n0 + lr) * K + kb + lc;

    float acc[4][4] = {};

    for (int kt = 0; kt < klen; kt += 16) {
        float4 av = *(const float4*)(Ag + kt);
        float4 bv = *(const float4*)(Bg + kt);
        As[lc+0][lr] = av.x; As[lc+1][lr] = av.y; As[lc+2][lr] = av.z; As[lc+3][lr] = av.w;
        Bs[lc+0][lr] = bv.x; Bs[lc+1][lr] = bv.y; Bs[lc+2][lr] = bv.z; Bs[lc+3][lr] = bv.w;
        __syncthreads();
        #pragma unroll
        for (int k = 0; k < 16; k++) {
            float4 a  = *(const float4*)&As[k][ty*4];
            float4 b4 = *(const float4*)&Bs[k][tx*4];
            acc[0][0] += a.x*b4.x; acc[0][1] += a.x*b4.y; acc[0][2] += a.x*b4.z; acc[0][3] += a.x*b4.w;
            acc[1][0] += a.y*b4.x; acc[1][1] += a.y*b4.y; acc[1][2] += a.y*b4.z; acc[1][3] += a.y*b4.w;
            acc[2][0] += a.z*b4.x; acc[2][1] += a.z*b4.y; acc[2][2] += a.z*b4.z; acc[2][3] += a.z*b4.w;
            acc[3][0] += a.w*b4.x; acc[3][1] += a.w*b4.y; acc[3][2] += a.w*b4.z; acc[3][3] += a.w*b4.w;
        }
        __syncthreads();
    }

    int col = n0 + tx * 4;
    if (ksplit == 1) {
        float4 bb = *(const float4*)&bias[col];
        #pragma unroll
        for (int i = 0; i < 4; i++) {
            int row = m0 + ty * 4 + i;
            float4 o = make_float4(acc[i][0] + bb.x, acc[i][1] + bb.y,
                                   acc[i][2] + bb.z, acc[i][3] + bb.w);
            if (epi == 1) { o.x = tanhf(o.x); o.y = tanhf(o.y); o.z = tanhf(o.z); o.w = tanhf(o.w); }
            *(float4*)&C[(size_t)row * N + col] = o;
        }
    } else {
        float* P = g_part + (size_t)blockIdx.z * M * N;
        #pragma unroll
        for (int i = 0; i < 4; i++) {
            int row = m0 + ty * 4 + i;
            *(float4*)&P[(size_t)row * N + col] =
                make_float4(acc[i][0], acc[i][1], acc[i][2], acc[i][3]);
        }
    }
}

// ---------------- K-split reduction + bias + optional tanh ----------------
__global__ void k_reduce(float* __restrict__ C, const float* __restrict__ bias,
                         int M, int N, int ksplit, int epi)
{
    int idx = blockIdx.x * blockDim.x + threadIdx.x;
    if (idx >= M * N) return;
    float acc = bias[idx % N];
    for (int z = 0; z < ksplit; z++) acc += g_part[(size_t)z * M * N + idx];
    if (epi) acc = tanhf(acc);
    C[idx] = acc;
}

// ---------------- GRU cell elementwise ----------------
__global__ void k_gru_cell(const float* __restrict__ hprev,
                           float* __restrict__ out_h,        // scratch (contig) or null
                           float* __restrict__ out_hidden,   // d_out slot (contig)
                           float* __restrict__ out_concat)   // stride-H2 slot or null
{
    int idx = blockIdx.x * blockDim.x + threadIdx.x;   // < B*H
    int b = idx >> 10, h = idx & 1023;
    float ir = g_gi[b*H3 + h],        hr = g_gh[b*H3 + h];
    float iz = g_gi[b*H3 + HH + h],   hz = g_gh[b*H3 + HH + h];
    float in = g_gi[b*H3 + 2*HH + h], hn = g_gh[b*H3 + 2*HH + h];
    float r = 1.f / (1.f + expf(-(ir + hr)));
    float z = 1.f / (1.f + expf(-(iz + hz)));
    float n = tanhf(in + r * hn);
    float ho = (1.f - z) * n + z * hprev[idx];
    if (out_h)      out_h[idx] = ho;
    out_hidden[idx] = ho;
    if (out_concat) out_concat[b * H2 + h] = ho;
}

// ---------------- fused attention: one CTA per batch element ----------------
// scores[s] = u2 . enc[s,b,:]  -> softmax over s -> attn out + context[b,:]
__global__ void __launch_bounds__(256) k_attn(const float* __restrict__ enc,
                                              float* __restrict__ attn_out)
{
    __shared__ float su[HH];
    __shared__ float sc[SS];
    __shared__ float red[32];

    int b = blockIdx.x;
    int tid = threadIdx.x;
    int warp = tid >> 5, lane = tid & 31;

    for (int i = tid; i < HH; i += 256) su[i] = g_u2[i];
    __syncthreads();

    // scores: each warp handles s = warp, warp+8, ...
    for (int s = warp; s < SS; s += 8) {
        const float* e = enc + ((size_t)s * BB + b) * HH;
        float acc = 0.f;
        for (int h = lane; h < HH; h += 32) acc += e[h] * su[h];
        #pragma unroll
        for (int o = 16; o; o >>= 1) acc += __shfl_xor_sync(0xffffffffu, acc, o);
        if (lane == 0) sc[s] = acc;
    }
    __syncthreads();

    // softmax over 256 scores (one per thread)
    float val = sc[tid];
    float m = val;
    #pragma unroll
    for (int o = 16; o; o >>= 1) m = fmaxf(m, __shfl_xor_sync(0xffffffffu, m, o));
    if (lane == 0) red[warp] = m;
    __syncthreads();
    if (tid == 0) {
        float t = red[0];
        for (int w = 1; w < 8; w++) t = fmaxf(t, red[w]);
        red[8] = t;
    }
    __syncthreads();
    float mx = red[8];
    float ev = expf(val - mx);
    float ssum = ev;
    #pragma unroll
    for (int o = 16; o; o >>= 1) ssum += __shfl_xor_sync(0xffffffffu, ssum, o);
    if (lane == 0) red[16 + warp] = ssum;
    __syncthreads();
    if (tid == 0) {
        float t = 0.f;
        for (int w = 0; w < 8; w++) t += red[16 + w];
        red[24] = 1.f / t;
    }
    __syncthreads();
    float w = ev * red[24];
    sc[tid] = w;
    attn_out[b * SS + tid] = w;
    __syncthreads();

    // context[b,h] = sum_s w[s] * enc[s,b,h]
    for (int h = tid; h < HH; h += 256) {
        const float* eb = enc + (size_t)b * HH + h;
        float acc = 0.f;
        #pragma unroll 4
        for (int s = 0; s < SS; s++) acc += sc[s] * eb[(size_t)s * BB * HH];
        g_concat[b * H2 + HH + h] = acc;
    }
}

// ---------------- host launcher ----------------
extern "C" void kernel_launch(void* const* d_in, const int* in_sizes, int n_in,
                              void* d_out, int out_size)
{
    const int*   ids      = (const int*)  d_in[0];
    const float* hidden   = (const float*)d_in[1];
    const float* enc      = (const float*)d_in[2];
    const float* embed    = (const float*)d_in[3];
    const float* W_attn   = (const float*)d_in[4];
    // d_in[5] = b_attn: provably cancels in softmax — unused
    const float* v        = (const float*)d_in[6];
    const float* w_ih0    = (const float*)d_in[7];
    const float* w_hh0    = (const float*)d_in[8];
    const float* b_ih0    = (const float*)d_in[9];
    const float* b_hh0    = (const float*)d_in[10];
    const float* w_ih1    = (const float*)d_in[11];
    const float* w_hh1    = (const float*)d_in[12];
    const float* b_ih1    = (const float*)d_in[13];
    const float* b_hh1    = (const float*)d_in[14];
    const float* W_concat = (const float*)d_in[15];
    const float* b_concat = (const float*)d_in[16];
    const float* W_out    = (const float*)d_in[17];
    const float* b_out    = (const float*)d_in[18];
    float* out = (float*)d_out;

    float *p_x, *p_gi, *p_gh, *p_h0, *p_concat, *p_cout;
    cudaGetSymbolAddress((void**)&p_x,      g_x);
    cudaGetSymbolAddress((void**)&p_gi,     g_gi);
    cudaGetSymbolAddress((void**)&p_gh,     g_gh);
    cudaGetSymbolAddress((void**)&p_h0,     g_h0);
    cudaGetSymbolAddress((void**)&p_concat, g_concat);
    cudaGetSymbolAddress((void**)&p_cout,   g_cout);

    // independent prologue: embed + attention (attention doesn't need rnn_out)
    k_embed<<<BB, 256>>>(ids, embed);
    k_u2<<<HH/256, 256>>>(W_attn, v);
    k_attn<<<BB, 256>>>(enc, out + OUT_ATTN);

    dim3 blk(256);
    dim3 gGRU(H3/64, BB/64, 4);     // K-split 4
    int  rGRU = (BB*H3 + 255)/256;

    // ---- GRU layer 0 ----
    k_gemm_nt<<<gGRU, blk>>>(p_x, w_ih0, p_gi, b_ih0, BB, H3, HH, 0);
    k_reduce<<<rGRU, 256>>>(p_gi, b_ih0, BB, H3, 4, 0);
    k_gemm_nt<<<gGRU, blk>>>(hidden, w_hh0, p_gh, b_hh0, BB, H3, HH, 0);
    k_reduce<<<rGRU, 256>>>(p_gh, b_hh0, BB, H3, 4, 0);
    k_gru_cell<<<(BB*HH)/256, 256>>>(hidden, p_h0, out + OUT_HID, nullptr);

    // ---- GRU layer 1 ----
    k_gemm_nt<<<gGRU, blk>>>(p_h0, w_ih1, p_gi, b_ih1, BB, H3, HH, 0);
    k_reduce<<<rGRU, 256>>>(p_gi, b_ih1, BB, H3, 4, 0);
    k_gemm_nt<<<gGRU, blk>>>(hidden + BB*HH, w_hh1, p_gh, b_hh1, BB, H3, HH, 0);
    k_reduce<<<rGRU, 256>>>(p_gh, b_hh1, BB, H3, 4, 0);
    k_gru_cell<<<(BB*HH)/256, 256>>>(hidden + BB*HH, nullptr,
                                     out + OUT_HID + BB*HH, p_concat);

    // ---- concat + tanh: [h1|context] @ W_concat^T ----
    dim3 gCat(HH/64, BB/64, 8);     // K-split 8 (K=2048)
    k_gemm_nt<<<gCat, blk>>>(p_concat, W_concat, p_cout, b_concat, BB, HH, H2, 1);
    k_reduce<<<(BB*HH + 255)/256, 256>>>(p_cout, b_concat, BB, HH, 8, 1);

    // ---- vocab projection: 128 x 32000 x 1024 ----
    dim3 gOut(VV/64, BB/64, 1);
    k_gemm_nt<<<gOut, blk>>>(p_cout, W_out, out, b_out, BB, VV, HH, 0);
}

// round 4
// speedup vs baseline: 1.6337x; 1.6337x over previous
#include <cuda_runtime.h>
#include <cuda_bf16.h>
#include <cstdint>
#include <math.h>

// Problem dims
#define BB 128
#define HH 1024
#define SS 256
#define VV 32000
#define H3 3072
#define H2 2048

#define OUT_HID  (BB*VV)
#define OUT_ATTN (BB*VV + 2*BB*HH)

// ---------------- scratch ----------------
__device__ float g_x[BB*HH];
__device__ float g_gi[BB*H3];
__device__ float g_gh[BB*H3];
__device__ float g_h0[BB*HH];
__device__ float g_concat[BB*H2];
__device__ float g_u2[HH];
__device__ float g_cout[BB*HH];
__device__ float g_part[8*BB*HH];   // K-split partials (concat GEMM)

// ---------------- helpers ----------------
__device__ __forceinline__ uint32_t smem_u32(const void* p) {
    uint32_t a;
    asm("{ .reg .u64 t; cvta.to.shared.u64 t, %1; cvt.u32.u64 %0, t; }" : "=r"(a) : "l"(p));
    return a;
}

#define SWZ(b) ((b) ^ (((b) >> 3) & 0x70))

#define LDSM_X4(r0, r1, r2, r3, a) \
    asm volatile("ldmatrix.sync.aligned.m8n8.x4.shared.b16 {%0,%1,%2,%3}, [%4];" \
        : "=r"(r0), "=r"(r1), "=r"(r2), "=r"(r3) : "r"(a))

__device__ __forceinline__ void mma16816(float* c, const uint32_t* a, const uint32_t* b) {
    asm volatile("mma.sync.aligned.m16n8k16.row.col.f32.bf16.bf16.f32 "
        "{%0,%1,%2,%3}, {%4,%5,%6,%7}, {%8,%9}, {%0,%1,%2,%3};"
        : "+f"(c[0]), "+f"(c[1]), "+f"(c[2]), "+f"(c[3])
        : "r"(a[0]), "r"(a[1]), "r"(a[2]), "r"(a[3]), "r"(b[0]), "r"(b[1]));
}

__device__ __forceinline__ uint32_t pk_bf16(__nv_bfloat16 x, __nv_bfloat16 y) {
    return (uint32_t)__bfloat16_as_ushort(x) | ((uint32_t)__bfloat16_as_ushort(y) << 16);
}

// fp32x4 -> bf16 hi/lo split (3-term compensated product source)
__device__ __forceinline__ void cvt_split(float4 f, uint2& hi, uint2& lo) {
    __nv_bfloat16 hx = __float2bfloat16_rn(f.x);
    __nv_bfloat16 hy = __float2bfloat16_rn(f.y);
    __nv_bfloat16 hz = __float2bfloat16_rn(f.z);
    __nv_bfloat16 hw = __float2bfloat16_rn(f.w);
    __nv_bfloat16 lx = __float2bfloat16_rn(f.x - __bfloat162float(hx));
    __nv_bfloat16 ly = __float2bfloat16_rn(f.y - __bfloat162float(hy));
    __nv_bfloat16 lz = __float2bfloat16_rn(f.z - __bfloat162float(hz));
    __nv_bfloat16 lw = __float2bfloat16_rn(f.w - __bfloat162float(hw));
    hi = make_uint2(pk_bf16(hx, hy), pk_bf16(hz, hw));
    lo = make_uint2(pk_bf16(lx, ly), pk_bf16(lz, lw));
}

// ============ HMMA GEMM: C[128, N] = A[128,K] @ B[N,K]^T (+bias, +tanh) ============
// bf16 3-split. M=128 fixed, NT columns per CTA, BK=64, double-buffered smem.
// 8 warps = 2 (M) x 4 (N); each warp 64 x NT/4 via m16n8k16.
// Smem stage layout: A_hi @0 (16KB), A_lo @16K, B_hi @32K (NT*128), B_lo after.
struct GemmArgs {
    const float* A; const float* B; float* C; const float* bias;
    int N; int K;
};

template<int NT, int KSPLIT, bool TANH>
__global__ void __launch_bounds__(256, 1) k_hmma(GemmArgs a0, GemmArgs a1)
{
    extern __shared__ char sm[];
    const GemmArgs g = (blockIdx.y == 0) ? a0 : a1;
    constexpr int NTILES = NT / 32;                 // n8 tiles per warp
    constexpr int STAGE = 32768 + 2 * NT * 128;

    const int tid = threadIdx.x;
    const int wid = tid >> 5, lane = tid & 31;
    const int warp_m = wid >> 2, warp_n = wid & 3;
    const int n0 = blockIdx.x * NT;
    const int K = g.K;
    const int kb0 = blockIdx.z * (K / KSPLIT);
    const int nch = (K / KSPLIT) >> 6;

    const uint32_t sbase = smem_u32(sm);
    const uint32_t lrow = (uint32_t)(lane & 15) * 128;
    const uint32_t xorv = (uint32_t)(lane & 7);
    const uint32_t kh   = (uint32_t)((lane >> 4) & 1);

    auto load_stage = [&](int ch, int st) {
        char* s = sm + st * STAGE;
        const int kb = kb0 + (ch << 6);
        #pragma unroll
        for (int i = 0; i < 8; i++) {                 // A: 128x64 fp32
            int idx = tid + i * 256;
            int row = idx >> 4, c4 = idx & 15;
            float4 f = *(const float4*)(g.A + (size_t)row * K + kb + c4 * 4);
            uint2 hi, lo; cvt_split(f, hi, lo);
            uint32_t off = SWZ((uint32_t)(row * 128 + c4 * 8));
            *(uint2*)(s + off)         = hi;
            *(uint2*)(s + 16384 + off) = lo;
        }
        #pragma unroll
        for (int i = 0; i < NT / 16; i++) {           // B: NTx64 fp32
            int idx = tid + i * 256;
            int row = idx >> 4, c4 = idx & 15;
            float4 f = *(const float4*)(g.B + (size_t)(n0 + row) * K + kb + c4 * 4);
            uint2 hi, lo; cvt_split(f, hi, lo);
            uint32_t off = SWZ((uint32_t)(row * 128 + c4 * 8));
            *(uint2*)(s + 32768 + off)            = hi;
            *(uint2*)(s + 32768 + NT * 128 + off) = lo;
        }
    };

    float acc[4][NTILES][4];
    #pragma unroll
    for (int a = 0; a < 4; a++)
        #pragma unroll
        for (int b = 0; b < NTILES; b++)
            #pragma unroll
            for (int c = 0; c < 4; c++) acc[a][b][c] = 0.f;

    load_stage(0, 0);
    __syncthreads();

    for (int ch = 0; ch < nch; ch++) {
        if (ch + 1 < nch) load_stage(ch + 1, (ch + 1) & 1);
        const uint32_t base = sbase + (uint32_t)(ch & 1) * STAGE;
        const uint32_t aH = base + (uint32_t)(warp_m * 64) * 128 + lrow;
        const uint32_t bH = base + 32768 + (uint32_t)(warp_n * (NT / 4)) * 128 + lrow;
        #pragma unroll
        for (int ks = 0; ks < 4; ks++) {
            const uint32_t koff = ((((uint32_t)(ks << 1) | kh) ^ xorv) << 4);
            uint32_t ahi[4][4], alo[4][4];
            #pragma unroll
            for (int mt = 0; mt < 4; mt++) {
                uint32_t ad = aH + mt * 2048 + koff;
                LDSM_X4(ahi[mt][0], ahi[mt][1], ahi[mt][2], ahi[mt][3], ad);
                LDSM_X4(alo[mt][0], alo[mt][1], alo[mt][2], alo[mt][3], ad + 16384);
            }
            uint32_t bhi[NTILES][2], blo[NTILES][2];
            #pragma unroll
            for (int bg = 0; bg < NT / 64; bg++) {
                uint32_t bd = bH + bg * 2048 + koff;
                uint32_t r0, r1, r2, r3;
                LDSM_X4(r0, r1, r2, r3, bd);
                bhi[2*bg][0] = r0; bhi[2*bg+1][0] = r1;
                bhi[2*bg][1] = r2; bhi[2*bg+1][1] = r3;
                LDSM_X4(r0, r1, r2, r3, bd + NT * 128);
                blo[2*bg][0] = r0; blo[2*bg+1][0] = r1;
                blo[2*bg][1] = r2; blo[2*bg+1][1] = r3;
            }
            #pragma unroll
            for (int mt = 0; mt < 4; mt++)
                #pragma unroll
                for (int nt = 0; nt < NTILES; nt++) {
                    mma16816(acc[mt][nt], ahi[mt], bhi[nt]);
                    mma16816(acc[mt][nt], ahi[mt], blo[nt]);
                    mma16816(acc[mt][nt], alo[mt], bhi[nt]);
                }
        }
        __syncthreads();
    }

    // ---- epilogue ----
    const int rl = lane >> 2;
    const int cl = (lane & 3) * 2;
    #pragma unroll
    for (int mt = 0; mt < 4; mt++) {
        const int r = warp_m * 64 + mt * 16 + rl;
        #pragma unroll
        for (int nt = 0; nt < NTILES; nt++) {
            const int c = n0 + warp_n * (NT / 4) + nt * 8 + cl;
            if (KSPLIT == 1) {
                float2 bb = *(const float2*)&g.bias[c];
                float2 o0 = make_float2(acc[mt][nt][0] + bb.x, acc[mt][nt][1] + bb.y);
                float2 o1 = make_float2(acc[mt][nt][2] + bb.x, acc[mt][nt][3] + bb.y);
                if (TANH) {
                    o0.x = tanhf(o0.x); o0.y = tanhf(o0.y);
                    o1.x = tanhf(o1.x); o1.y = tanhf(o1.y);
                }
                *(float2*)&g.C[(size_t)r * g.N + c]       = o0;
                *(float2*)&g.C[(size_t)(r + 8) * g.N + c] = o1;
            } else {
                float* P = g_part + (size_t)blockIdx.z * 128 * g.N;
                *(float2*)&P[(size_t)r * g.N + c] =
                    make_float2(acc[mt][nt][0], acc[mt][nt][1]);
                *(float2*)&P[(size_t)(r + 8) * g.N + c] =
                    make_float2(acc[mt][nt][2], acc[mt][nt][3]);
            }
        }
    }
}

// ---------------- K-split reduction + bias + optional tanh ----------------
__global__ void k_reduce(float* __restrict__ C, const float* __restrict__ bias,
                         int M, int N, int ksplit, int epi)
{
    int idx = blockIdx.x * blockDim.x + threadIdx.x;
    if (idx >= M * N) return;
    float acc = bias[idx % N];
    for (int z = 0; z < ksplit; z++) acc += g_part[(size_t)z * M * N + idx];
    if (epi) acc = tanhf(acc);
    C[idx] = acc;
}

// ---------------- embedding gather ----------------
__global__ void k_embed(const int* __restrict__ ids, const float* __restrict__ tab) {
    int b = blockIdx.x;
    long row = ids[b];
    const float4* src = (const float4*)(tab + row * (long)HH);
    float4* dst = (float4*)(g_x + b * HH);
    for (int i = threadIdx.x; i < HH/4; i += blockDim.x) dst[i] = src[i];
}

// ---------------- u2[e] = sum_h v[h] * W_attn[h, H+e] ----------------
__global__ void k_u2(const float* __restrict__ W_attn, const float* __restrict__ v) {
    int e = blockIdx.x * blockDim.x + threadIdx.x;
    float acc = 0.f;
    #pragma unroll 4
    for (int h = 0; h < HH; h++) acc += v[h] * W_attn[h * H2 + HH + e];
    g_u2[e] = acc;
}

// ---------------- GRU cell elementwise ----------------
__global__ void k_gru_cell(const float* __restrict__ hprev,
                           float* __restrict__ out_h,
                           float* __restrict__ out_hidden,
                           float* __restrict__ out_concat)
{
    int idx = blockIdx.x * blockDim.x + threadIdx.x;
    int b = idx >> 10, h = idx & 1023;
    float ir = g_gi[b*H3 + h],        hr = g_gh[b*H3 + h];
    float iz = g_gi[b*H3 + HH + h],   hz = g_gh[b*H3 + HH + h];
    float in = g_gi[b*H3 + 2*HH + h], hn = g_gh[b*H3 + 2*HH + h];
    float r = 1.f / (1.f + expf(-(ir + hr)));
    float z = 1.f / (1.f + expf(-(iz + hz)));
    float n = tanhf(in + r * hn);
    float ho = (1.f - z) * n + z * hprev[idx];
    if (out_h)      out_h[idx] = ho;
    out_hidden[idx] = ho;
    if (out_concat) out_concat[b * H2 + h] = ho;
}

// ---------------- one-pass online-softmax attention ----------------
__global__ void __launch_bounds__(256) k_attn(const float* __restrict__ enc,
                                              float* __restrict__ attn_out)
{
    __shared__ __align__(16) float su[HH];
    __shared__ __align__(16) float cacc[HH];
    __shared__ __align__(16) float rows[8][HH];
    __shared__ float sc[SS];
    __shared__ float s_m, s_z, s_alpha, s_p[8];

    int b = blockIdx.x;
    int tid = threadIdx.x;
    int warp = tid >> 5, lane = tid & 31;

    for (int i = tid; i < HH; i += 256) { su[i] = g_u2[i]; cacc[i] = 0.f; }
    if (tid == 0) { s_m = -1e30f; s_z = 0.f; }
    __syncthreads();

    for (int s0 = 0; s0 < SS; s0 += 8) {
        #pragma unroll
        for (int i = 0; i < 8; i++) {
            int idx = tid + i * 256;
            int j = idx >> 8, c = idx & 255;
            ((float4*)rows[j])[c] =
                ((const float4*)(enc + ((size_t)(s0 + j) * BB + b) * HH))[c];
        }
        __syncthreads();
        {
            float acc = 0.f;
            const float* r = rows[warp];
            #pragma unroll
            for (int h = lane * 4; h < HH; h += 128) {
                float4 rv = *(const float4*)&r[h];
                float4 uv = *(const float4*)&su[h];
                acc += rv.x*uv.x + rv.y*uv.y + rv.z*uv.z + rv.w*uv.w;
            }
            #pragma unroll
            for (int o = 16; o; o >>= 1) acc += __shfl_xor_sync(0xffffffffu, acc, o);
            if (lane == 0) sc[s0 + warp] = acc;
        }
        __syncthreads();
        if (tid == 0) {
            float m_new = s_m;
            #pragma unroll
            for (int j = 0; j < 8; j++) m_new = fmaxf(m_new, sc[s0 + j]);
            float alpha = expf(s_m - m_new);
            float zz = s_z * alpha;
            #pragma unroll
            for (int j = 0; j < 8; j++) { float p = expf(sc[s0 + j] - m_new); s_p[j] = p; zz += p; }
            s_alpha = alpha; s_m = m_new; s_z = zz;
        }
        __syncthreads();
        float alpha = s_alpha;
        float p0 = s_p[0], p1 = s_p[1], p2 = s_p[2], p3 = s_p[3];
        float p4 = s_p[4], p5 = s_p[5], p6 = s_p[6], p7 = s_p[7];
        #pragma unroll
        for (int h = tid; h < HH; h += 256) {
            float c = cacc[h] * alpha;
            c += p0*rows[0][h] + p1*rows[1][h] + p2*rows[2][h] + p3*rows[3][h];
            c += p4*rows[4][h] + p5*rows[5][h] + p6*rows[6][h] + p7*rows[7][h];
            cacc[h] = c;
        }
        __syncthreads();
    }

    float inv = 1.f / s_z, m = s_m;
    attn_out[b * SS + tid] = expf(sc[tid] - m) * inv;
    for (int h = tid; h < HH; h += 256)
        g_concat[b * H2 + HH + h] = cacc[h] * inv;
}

// ---------------- host launcher ----------------
extern "C" void kernel_launch(void* const* d_in, const int* in_sizes, int n_in,
                              void* d_out, int out_size)
{
    const int*   ids      = (const int*)  d_in[0];
    const float* hidden   = (const float*)d_in[1];
    const float* enc      = (const float*)d_in[2];
    const float* embed    = (const float*)d_in[3];
    const float* W_attn   = (const float*)d_in[4];
    // d_in[5] = b_attn: cancels in softmax — unused
    const float* v        = (const float*)d_in[6];
    const float* w_ih0    = (const float*)d_in[7];
    const float* w_hh0    = (const float*)d_in[8];
    const float* b_ih0    = (const float*)d_in[9];
    const float* b_hh0    = (const float*)d_in[10];
    const float* w_ih1    = (const float*)d_in[11];
    const float* w_hh1    = (const float*)d_in[12];
    const float* b_ih1    = (const float*)d_in[13];
    const float* b_hh1    = (const float*)d_in[14];
    const float* W_concat = (const float*)d_in[15];
    const float* b_concat = (const float*)d_in[16];
    const float* W_out    = (const float*)d_in[17];
    const float* b_out    = (const float*)d_in[18];
    float* out = (float*)d_out;

    float *p_x, *p_gi, *p_gh, *p_h0, *p_concat, *p_cout;
    cudaGetSymbolAddress((void**)&p_x,      g_x);
    cudaGetSymbolAddress((void**)&p_gi,     g_gi);
    cudaGetSymbolAddress((void**)&p_gh,     g_gh);
    cudaGetSymbolAddress((void**)&p_h0,     g_h0);
    cudaGetSymbolAddress((void**)&p_concat, g_concat);
    cudaGetSymbolAddress((void**)&p_cout,   g_cout);

    const int smem64  = 2 * (32768 + 2 * 64  * 128);   // 98304
    const int smem128 = 2 * (32768 + 2 * 128 * 128);   // 131072
    cudaFuncSetAttribute(k_hmma<64,1,false>,  cudaFuncAttributeMaxDynamicSharedMemorySize, smem64);
    cudaFuncSetAttribute(k_hmma<128,1,false>, cudaFuncAttributeMaxDynamicSharedMemorySize, smem128);
    cudaFuncSetAttribute(k_hmma<128,8,false>, cudaFuncAttributeMaxDynamicSharedMemorySize, smem128);

    // prologue (independent of GRU)
    k_embed<<<BB, 256>>>(ids, embed);
    k_u2<<<HH/256, 256>>>(W_attn, v);
    k_attn<<<BB, 256>>>(enc, out + OUT_ATTN);

    // ---- GRU layer 0: gi = x@w_ih0^T ; gh = h@w_hh0^T (dual gemm via grid.y) ----
    {
        GemmArgs gi{p_x,    w_ih0, p_gi, b_ih0, H3, HH};
        GemmArgs gh{hidden, w_hh0, p_gh, b_hh0, H3, HH};
        k_hmma<64,1,false><<<dim3(H3/64, 2, 1), 256, smem64>>>(gi, gh);
    }
    k_gru_cell<<<(BB*HH)/256, 256>>>(hidden, p_h0, out + OUT_HID, nullptr);

    // ---- GRU layer 1 ----
    {
        GemmArgs gi{p_h0,           w_ih1, p_gi, b_ih1, H3, HH};
        GemmArgs gh{hidden + BB*HH, w_hh1, p_gh, b_hh1, H3, HH};
        k_hmma<64,1,false><<<dim3(H3/64, 2, 1), 256, smem64>>>(gi, gh);
    }
    k_gru_cell<<<(BB*HH)/256, 256>>>(hidden + BB*HH, nullptr,
                                     out + OUT_HID + BB*HH, p_concat);

    // ---- concat + tanh: [h1|context] @ W_concat^T, K=2048 split 8 ways ----
    {
        GemmArgs gc{p_concat, W_concat, p_cout, b_concat, HH, H2};
        k_hmma<128,8,false><<<dim3(HH/128, 1, 8), 256, smem128>>>(gc, gc);
    }
    k_reduce<<<(BB*HH + 255)/256, 256>>>(p_cout, b_concat, BB, HH, 8, 1);

    // ---- vocab projection: 128 x 32000 x 1024 ----
    {
        GemmArgs go{p_cout, W_out, out, b_out, VV, HH};
        k_hmma<128,1,false><<<dim3(VV/128, 1, 1), 256, smem128>>>(go, go);
    }
}